// round 10
// baseline (speedup 1.0000x reference)
#include <cuda_runtime.h>
#include <cuda_fp16.h>
#include <math.h>
#include <stdint.h>

// Problem dims (fixed)
#define BATCH 4
#define SEQ   8192
#define DIM   512
#define HEADS 8
#define MROWS (BATCH*SEQ)

// scan chunking
#define CHUNK  128
#define NCHUNK (SEQ/CHUNK)

// ---------------------------------------------------------------------------
// device scratch (allocation-free rule -> __device__ globals)
// ---------------------------------------------------------------------------
__device__ float  g_xp [(size_t)MROWS*DIM];     // GEMM1 output (fp32)
__device__ float  g_s  [(size_t)MROWS*DIM];     // local-scan scratch (fp32)
__device__ __half g_xh [(size_t)MROWS*DIM];     // x as fp16
__device__ __half g_yh [(size_t)MROWS*DIM];     // y as fp16
__device__ __half g_w1 [DIM*DIM];               // W_in  fp16
__device__ __half g_w2 [DIM*DIM];               // W_out fp16
__device__ float  g_e  [(size_t)BATCH*NCHUNK*DIM];
__device__ int    g_flag[BATCH*NCHUNK];
__device__ float  g_alpha[HEADS];

// ---------------------------------------------------------------------------
// helpers
// ---------------------------------------------------------------------------
__device__ __forceinline__ uint32_t s2u(const void* p) {
    uint32_t a;
    asm("{ .reg .u64 t; cvta.to.shared.u64 t, %1; cvt.u32.u64 %0, t; }"
        : "=r"(a) : "l"(p));
    return a;
}

__device__ __forceinline__ void ldsm4(uint32_t& r0, uint32_t& r1,
                                      uint32_t& r2, uint32_t& r3,
                                      uint32_t addr) {
    asm volatile("ldmatrix.sync.aligned.m8n8.x4.shared.b16 {%0,%1,%2,%3}, [%4];"
                 : "=r"(r0), "=r"(r1), "=r"(r2), "=r"(r3) : "r"(addr));
}

__device__ __forceinline__ void mma16816(float* c, const uint32_t* a,
                                         const uint32_t* b) {
    asm volatile(
        "mma.sync.aligned.m16n8k16.row.col.f32.f16.f16.f32 "
        "{%0,%1,%2,%3}, {%4,%5,%6,%7}, {%8,%9}, {%0,%1,%2,%3};"
        : "+f"(c[0]), "+f"(c[1]), "+f"(c[2]), "+f"(c[3])
        : "r"(a[0]), "r"(a[1]), "r"(a[2]), "r"(a[3]), "r"(b[0]), "r"(b[1]));
}

__device__ __forceinline__ int ld_acq(const int* p) {
    int v;
    asm volatile("ld.acquire.gpu.global.b32 %0, [%1];" : "=r"(v) : "l"(p) : "memory");
    return v;
}
__device__ __forceinline__ void st_rel(int* p, int v) {
    asm volatile("st.release.gpu.global.b32 [%0], %1;" :: "l"(p), "r"(v) : "memory");
}

// ---------------------------------------------------------------------------
// alpha = sigmoid(alpha_param);  also zero lookback flags (256 of them)
// ---------------------------------------------------------------------------
__global__ void prep_kernel(const float* __restrict__ ap) {
    int t = threadIdx.x;
    if (t < HEADS) g_alpha[t] = 1.0f / (1.0f + expf(-ap[t]));
    if (t < BATCH * NCHUNK) g_flag[t] = 0;
}

// ---------------------------------------------------------------------------
// fp32 -> fp16 convert (vectorized by 4)
// ---------------------------------------------------------------------------
__global__ void __launch_bounds__(256)
convx_kernel(const float* __restrict__ src, __half* __restrict__ dst, int n4) {
    int i = blockIdx.x * blockDim.x + threadIdx.x;
    if (i >= n4) return;
    float4 v = ((const float4*)src)[i];
    __half2 h0 = __halves2half2(__float2half_rn(v.x), __float2half_rn(v.y));
    __half2 h1 = __halves2half2(__float2half_rn(v.z), __float2half_rn(v.w));
    ((__half2*)(dst + 4*(size_t)i))[0] = h0;
    ((__half2*)(dst + 4*(size_t)i))[1] = h1;
}

// ---------------------------------------------------------------------------
// fp16 HMMA GEMM (R9-proven): C[m,n] = sum_k A[m,k]*B[n,k] + bias[n]
//   CTA 128x128, BK=64, 256 thr (8 warps 2x4), warp tile 64x32.
//   2-stage cp.async; xor swizzle; ldmatrix.x4; mma.m16n8k16.f16; 2 CTAs/SM.
// ---------------------------------------------------------------------------
#define BM 128
#define BN 128
#define BK 64
#define KITERS (DIM/BK)     // 8

#define XA_OFF 0
#define BB_OFF 16384
#define STAGE_BYTES 32768
#define SMEM_TOTAL (2*STAGE_BYTES)   // 64 KB

#define TSWZ(row, c16) ((uint32_t)(row) * 128u + 16u * ((uint32_t)(c16) ^ ((uint32_t)(row) & 7u)))

__device__ __forceinline__ void load_stage(uint32_t sbase,
                                           const __half* __restrict__ A,
                                           const __half* __restrict__ B,
                                           int m0, int n0, int k0, int tid) {
#pragma unroll
    for (int q = 0; q < 8; q++) {
        int i = tid + q * 256;
        int mat = i >> 10;            // 0 A, 1 B
        int j = i & 1023;
        int row = j >> 3;
        int c = j & 7;
        const __half* src = (mat ? B + (size_t)(n0 + row) * DIM
                                 : A + (size_t)(m0 + row) * DIM) + k0 + c * 8;
        uint32_t dst = sbase + (mat ? BB_OFF : XA_OFF) + TSWZ(row, c);
        asm volatile("cp.async.cg.shared.global [%0], [%1], 16;"
                     :: "r"(dst), "l"(src));
    }
}

__global__ void __launch_bounds__(256, 2)
gemm_mma(const __half* __restrict__ A, const __half* __restrict__ B,
         const float* __restrict__ bias, float* __restrict__ C) {
    extern __shared__ char smem[];
    uint32_t sb = s2u(smem);

    const int tid  = threadIdx.x;
    const int wid  = tid >> 5;
    const int lane = tid & 31;
    const int wm   = wid >> 2;
    const int wn   = wid & 3;
    const int m0   = blockIdx.y * BM;
    const int n0   = blockIdx.x * BN;

    float acc[4][4][4];
#pragma unroll
    for (int i = 0; i < 4; i++)
#pragma unroll
        for (int j = 0; j < 4; j++)
#pragma unroll
            for (int r = 0; r < 4; r++) acc[i][j][r] = 0.0f;

    const int arow = wm * 64 + (lane & 15);
    const int achk = lane >> 4;
    const int brow = wn * 32 + (lane & 7) + ((lane >> 4) << 3);
    const int bchk = (lane >> 3) & 1;
    const uint32_t sxor = (uint32_t)(lane & 7);

    load_stage(sb, A, B, m0, n0, 0, tid);
    asm volatile("cp.async.commit_group;" ::: "memory");

    for (int it = 0; it < KITERS; it++) {
        if (it + 1 < KITERS) {
            load_stage(sb + ((it + 1) & 1) * STAGE_BYTES,
                       A, B, m0, n0, (it + 1) * BK, tid);
            asm volatile("cp.async.commit_group;" ::: "memory");
            asm volatile("cp.async.wait_group 1;" ::: "memory");
        } else {
            asm volatile("cp.async.wait_group 0;" ::: "memory");
        }
        __syncthreads();

        uint32_t st = sb + (it & 1) * STAGE_BYTES;
#pragma unroll
        for (int ks = 0; ks < BK / 16; ks++) {
            uint32_t av[4][4];
#pragma unroll
            for (int mt = 0; mt < 4; mt++) {
                int row = arow + mt * 16;
                uint32_t co = (uint32_t)(2 * ks + achk) ^ sxor;
                uint32_t off = (uint32_t)row * 128u + co * 16u;
                ldsm4(av[mt][0], av[mt][1], av[mt][2], av[mt][3],
                      st + XA_OFF + off);
            }
            uint32_t bv[4][2];
#pragma unroll
            for (int nt2 = 0; nt2 < 2; nt2++) {
                int row = brow + nt2 * 16;
                uint32_t co = (uint32_t)(2 * ks + bchk) ^ sxor;
                uint32_t off = (uint32_t)row * 128u + co * 16u;
                uint32_t r0, r1, r2, r3;
                ldsm4(r0, r1, r2, r3, st + BB_OFF + off);
                bv[nt2*2][0] = r0; bv[nt2*2][1] = r1;
                bv[nt2*2+1][0] = r2; bv[nt2*2+1][1] = r3;
            }
#pragma unroll
            for (int mt = 0; mt < 4; mt++)
#pragma unroll
                for (int nt = 0; nt < 4; nt++)
                    mma16816(acc[mt][nt], av[mt], bv[nt]);
        }
        __syncthreads();
    }

    const int erow = m0 + wm * 64 + (lane >> 2);
    const int ecol = n0 + wn * 32 + 2 * (lane & 3);
#pragma unroll
    for (int nt = 0; nt < 4; nt++) {
        int col = ecol + nt * 8;
        float b0 = bias[col], b1 = bias[col + 1];
#pragma unroll
        for (int mt = 0; mt < 4; mt++) {
            int row = erow + mt * 16;
            float2 v0 = make_float2(acc[mt][nt][0] + b0, acc[mt][nt][1] + b1);
            float2 v1 = make_float2(acc[mt][nt][2] + b0, acc[mt][nt][3] + b1);
            *(float2*)(C + (size_t)row * DIM + col)       = v0;
            *(float2*)(C + (size_t)(row + 8) * DIM + col) = v1;
        }
    }
}

// ---------------------------------------------------------------------------
// Single-pass decoupled-lookback scan.
//   y[t] = a*y[t-1] + alpha*(xp[t]-xp[t-1]);  y[-1] = xp[-1] = init[d].
//   Per block: chunk c of batch b, thread = channel d.
//   Pass 1: local scan (zero init) -> s[t] (fp32 scratch, L2-hot), publish e.
//   Lookback: carry = fold(aN*carry + e[j]) over j<c, starting at init[d].
//   Pass 2: y[t] = s[t] + a^(t+1)*carry -> fp16.
//   All 256 blocks co-resident (512thr, ~30 regs, no smem) -> no deadlock.
// ---------------------------------------------------------------------------
__global__ void __launch_bounds__(512)
scan_onepass(const float* __restrict__ init_state) {
    const int d = threadIdx.x;
    const int c = blockIdx.x, b = blockIdx.y;
    const float alpha = g_alpha[d >> 6];
    const float a = 1.0f - alpha;
    const float aN = powf(a, (float)CHUNK);
    const int t0 = c * CHUNK;
    const size_t off = ((size_t)b * SEQ + t0) * DIM + d;
    const float* xp = g_xp + off;
    float* s = g_s + off;
    __half* y = g_yh + off;

    // pass 1: local scan with zero initial state
    float prev = (t0 == 0) ? init_state[d] : *(xp - DIM);
    float l = 0.0f;
#pragma unroll 4
    for (int t = 0; t < CHUNK; t++) {
        float cur = xp[(size_t)t * DIM];
        l = a * l + alpha * (cur - prev);
        prev = cur;
        s[(size_t)t * DIM] = l;
    }

    // publish chunk-terminal
    g_e[((size_t)b * NCHUNK + c) * DIM + d] = l;
    __syncthreads();
    __threadfence();
    if (d == 0) st_rel(&g_flag[b * NCHUNK + c], 1);

    // lookback fold
    float carry = init_state[d];
    for (int j = 0; j < c; j++) {
        const int* fp = &g_flag[b * NCHUNK + j];
        while (ld_acq(fp) == 0) {}
        carry = fmaf(aN, carry, g_e[((size_t)b * NCHUNK + j) * DIM + d]);
    }

    // pass 2: add carry contribution, emit fp16
    float w = a;
#pragma unroll 4
    for (int t = 0; t < CHUNK; t++) {
        float v = fmaf(w, carry, s[(size_t)t * DIM]);
        y[(size_t)t * DIM] = __float2half_rn(v);
        w *= a;
    }
}

// ---------------------------------------------------------------------------
// launch
// ---------------------------------------------------------------------------
extern "C" void kernel_launch(void* const* d_in, const int* in_sizes, int n_in,
                              void* d_out, int out_size) {
    const float* x    = (const float*)d_in[0];
    const float* Win  = (const float*)d_in[1];
    const float* bin  = (const float*)d_in[2];
    const float* Wout = (const float*)d_in[3];
    const float* bout = (const float*)d_in[4];
    const float* init = (const float*)d_in[5];
    const float* ap   = (const float*)d_in[6];
    float* out = (float*)d_out;

    cudaFuncSetAttribute(gemm_mma, cudaFuncAttributeMaxDynamicSharedMemorySize,
                         SMEM_TOTAL);

    prep_kernel<<<1, 256>>>(ap);

    __half *xh, *w1, *w2, *yh;
    float *xp;
    cudaGetSymbolAddress((void**)&xh, g_xh);
    cudaGetSymbolAddress((void**)&w1, g_w1);
    cudaGetSymbolAddress((void**)&w2, g_w2);
    cudaGetSymbolAddress((void**)&yh, g_yh);
    cudaGetSymbolAddress((void**)&xp, g_xp);

    int n4x = (MROWS * DIM) / 4;
    convx_kernel<<<(n4x + 255) / 256, 256>>>(x, xh, n4x);
    int n4w = (DIM * DIM) / 4;
    convx_kernel<<<(n4w + 255) / 256, 256>>>(Win,  w1, n4w);
    convx_kernel<<<(n4w + 255) / 256, 256>>>(Wout, w2, n4w);

    dim3 ggrid(DIM / BN, MROWS / BM);
    gemm_mma<<<ggrid, 256, SMEM_TOTAL>>>(xh, w1, bin, xp);

    scan_onepass<<<dim3(NCHUNK, BATCH), DIM>>>(init);

    gemm_mma<<<ggrid, 256, SMEM_TOTAL>>>(yh, w2, bout, out);
}

// round 11
// speedup vs baseline: 1.6594x; 1.6594x over previous
#include <cuda_runtime.h>
#include <cuda_fp16.h>
#include <math.h>
#include <stdint.h>

// Problem dims (fixed)
#define BATCH 4
#define SEQ   8192
#define DIM   512
#define HEADS 8
#define MROWS (BATCH*SEQ)

// scan chunking
#define CHUNK  128
#define NCHUNK (SEQ/CHUNK)

// ---------------------------------------------------------------------------
// device scratch (allocation-free rule -> __device__ globals)
// ---------------------------------------------------------------------------
__device__ __half g_xp [(size_t)MROWS*DIM];     // GEMM1 output (fp16)
__device__ __half g_xh [(size_t)MROWS*DIM];     // x as fp16
__device__ __half g_yh [(size_t)MROWS*DIM];     // y as fp16
__device__ __half g_w1 [DIM*DIM];               // W_in  fp16
__device__ __half g_w2 [DIM*DIM];               // W_out fp16
__device__ float  g_e  [(size_t)BATCH*NCHUNK*DIM];
__device__ float  g_cin[(size_t)BATCH*NCHUNK*DIM];
__device__ float  g_alpha[HEADS];

// ---------------------------------------------------------------------------
// helpers
// ---------------------------------------------------------------------------
__device__ __forceinline__ uint32_t s2u(const void* p) {
    uint32_t a;
    asm("{ .reg .u64 t; cvta.to.shared.u64 t, %1; cvt.u32.u64 %0, t; }"
        : "=r"(a) : "l"(p));
    return a;
}

__device__ __forceinline__ void ldsm4(uint32_t& r0, uint32_t& r1,
                                      uint32_t& r2, uint32_t& r3,
                                      uint32_t addr) {
    asm volatile("ldmatrix.sync.aligned.m8n8.x4.shared.b16 {%0,%1,%2,%3}, [%4];"
                 : "=r"(r0), "=r"(r1), "=r"(r2), "=r"(r3) : "r"(addr));
}

__device__ __forceinline__ void mma16816(float* c, const uint32_t* a,
                                         const uint32_t* b) {
    asm volatile(
        "mma.sync.aligned.m16n8k16.row.col.f32.f16.f16.f32 "
        "{%0,%1,%2,%3}, {%4,%5,%6,%7}, {%8,%9}, {%0,%1,%2,%3};"
        : "+f"(c[0]), "+f"(c[1]), "+f"(c[2]), "+f"(c[3])
        : "r"(a[0]), "r"(a[1]), "r"(a[2]), "r"(a[3]), "r"(b[0]), "r"(b[1]));
}

// ---------------------------------------------------------------------------
// alpha = sigmoid(alpha_param)
// ---------------------------------------------------------------------------
__global__ void alpha_kernel(const float* __restrict__ ap) {
    int h = threadIdx.x;
    if (h < HEADS) g_alpha[h] = 1.0f / (1.0f + expf(-ap[h]));
}

// ---------------------------------------------------------------------------
// fp32 -> fp16 convert (vectorized by 4)
// ---------------------------------------------------------------------------
__global__ void __launch_bounds__(256)
convx_kernel(const float* __restrict__ src, __half* __restrict__ dst, int n4) {
    int i = blockIdx.x * blockDim.x + threadIdx.x;
    if (i >= n4) return;
    float4 v = ((const float4*)src)[i];
    __half2 h0 = __halves2half2(__float2half_rn(v.x), __float2half_rn(v.y));
    __half2 h1 = __halves2half2(__float2half_rn(v.z), __float2half_rn(v.w));
    ((__half2*)(dst + 4*(size_t)i))[0] = h0;
    ((__half2*)(dst + 4*(size_t)i))[1] = h1;
}

// ---------------------------------------------------------------------------
// fp16 HMMA GEMM (R9-proven): C[m,n] = sum_k A[m,k]*B[n,k] + bias[n]
//   CTA 128x128, BK=64, 256 thr (8 warps 2x4), warp tile 64x32.
//   2-stage cp.async; xor swizzle; ldmatrix.x4; mma.m16n8k16.f16; 2 CTAs/SM.
//   Output type templated: GEMM1 -> __half (xp), GEMM2 -> float (final out).
// ---------------------------------------------------------------------------
#define BM 128
#define BN 128
#define BK 64
#define KITERS (DIM/BK)     // 8

#define XA_OFF 0
#define BB_OFF 16384
#define STAGE_BYTES 32768
#define SMEM_TOTAL (2*STAGE_BYTES)   // 64 KB

#define TSWZ(row, c16) ((uint32_t)(row) * 128u + 16u * ((uint32_t)(c16) ^ ((uint32_t)(row) & 7u)))

__device__ __forceinline__ void load_stage(uint32_t sbase,
                                           const __half* __restrict__ A,
                                           const __half* __restrict__ B,
                                           int m0, int n0, int k0, int tid) {
#pragma unroll
    for (int q = 0; q < 8; q++) {
        int i = tid + q * 256;
        int mat = i >> 10;            // 0 A, 1 B
        int j = i & 1023;
        int row = j >> 3;
        int c = j & 7;
        const __half* src = (mat ? B + (size_t)(n0 + row) * DIM
                                 : A + (size_t)(m0 + row) * DIM) + k0 + c * 8;
        uint32_t dst = sbase + (mat ? BB_OFF : XA_OFF) + TSWZ(row, c);
        asm volatile("cp.async.cg.shared.global [%0], [%1], 16;"
                     :: "r"(dst), "l"(src));
    }
}

template <typename OutT>
__global__ void __launch_bounds__(256, 2)
gemm_mma(const __half* __restrict__ A, const __half* __restrict__ B,
         const float* __restrict__ bias, OutT* __restrict__ C) {
    extern __shared__ char smem[];
    uint32_t sb = s2u(smem);

    const int tid  = threadIdx.x;
    const int wid  = tid >> 5;
    const int lane = tid & 31;
    const int wm   = wid >> 2;
    const int wn   = wid & 3;
    const int m0   = blockIdx.y * BM;
    const int n0   = blockIdx.x * BN;

    float acc[4][4][4];
#pragma unroll
    for (int i = 0; i < 4; i++)
#pragma unroll
        for (int j = 0; j < 4; j++)
#pragma unroll
            for (int r = 0; r < 4; r++) acc[i][j][r] = 0.0f;

    const int arow = wm * 64 + (lane & 15);
    const int achk = lane >> 4;
    const int brow = wn * 32 + (lane & 7) + ((lane >> 4) << 3);
    const int bchk = (lane >> 3) & 1;
    const uint32_t sxor = (uint32_t)(lane & 7);

    load_stage(sb, A, B, m0, n0, 0, tid);
    asm volatile("cp.async.commit_group;" ::: "memory");

    for (int it = 0; it < KITERS; it++) {
        if (it + 1 < KITERS) {
            load_stage(sb + ((it + 1) & 1) * STAGE_BYTES,
                       A, B, m0, n0, (it + 1) * BK, tid);
            asm volatile("cp.async.commit_group;" ::: "memory");
            asm volatile("cp.async.wait_group 1;" ::: "memory");
        } else {
            asm volatile("cp.async.wait_group 0;" ::: "memory");
        }
        __syncthreads();

        uint32_t st = sb + (it & 1) * STAGE_BYTES;
#pragma unroll
        for (int ks = 0; ks < BK / 16; ks++) {
            uint32_t av[4][4];
#pragma unroll
            for (int mt = 0; mt < 4; mt++) {
                int row = arow + mt * 16;
                uint32_t co = (uint32_t)(2 * ks + achk) ^ sxor;
                uint32_t off = (uint32_t)row * 128u + co * 16u;
                ldsm4(av[mt][0], av[mt][1], av[mt][2], av[mt][3],
                      st + XA_OFF + off);
            }
            uint32_t bv[4][2];
#pragma unroll
            for (int nt2 = 0; nt2 < 2; nt2++) {
                int row = brow + nt2 * 16;
                uint32_t co = (uint32_t)(2 * ks + bchk) ^ sxor;
                uint32_t off = (uint32_t)row * 128u + co * 16u;
                uint32_t r0, r1, r2, r3;
                ldsm4(r0, r1, r2, r3, st + BB_OFF + off);
                bv[nt2*2][0] = r0; bv[nt2*2][1] = r1;
                bv[nt2*2+1][0] = r2; bv[nt2*2+1][1] = r3;
            }
#pragma unroll
            for (int mt = 0; mt < 4; mt++)
#pragma unroll
                for (int nt = 0; nt < 4; nt++)
                    mma16816(acc[mt][nt], av[mt], bv[nt]);
        }
        __syncthreads();
    }

    const int erow = m0 + wm * 64 + (lane >> 2);
    const int ecol = n0 + wn * 32 + 2 * (lane & 3);
#pragma unroll
    for (int nt = 0; nt < 4; nt++) {
        int col = ecol + nt * 8;
        float b0 = bias[col], b1 = bias[col + 1];
#pragma unroll
        for (int mt = 0; mt < 4; mt++) {
            int row = erow + mt * 16;
            if (sizeof(OutT) == 4) {
                float2 v0 = make_float2(acc[mt][nt][0] + b0, acc[mt][nt][1] + b1);
                float2 v1 = make_float2(acc[mt][nt][2] + b0, acc[mt][nt][3] + b1);
                *(float2*)((float*)C + (size_t)row * DIM + col)       = v0;
                *(float2*)((float*)C + (size_t)(row + 8) * DIM + col) = v1;
            } else {
                __half2 h0 = __halves2half2(__float2half_rn(acc[mt][nt][0] + b0),
                                            __float2half_rn(acc[mt][nt][1] + b1));
                __half2 h1 = __halves2half2(__float2half_rn(acc[mt][nt][2] + b0),
                                            __float2half_rn(acc[mt][nt][3] + b1));
                *(__half2*)((__half*)C + (size_t)row * DIM + col)       = h0;
                *(__half2*)((__half*)C + (size_t)(row + 8) * DIM + col) = h1;
            }
        }
    }
}

// ---------------------------------------------------------------------------
// Chunked linear scan over fp16 xp:
//   y[t] = a*y[t-1] + alpha*(xp[t]-xp[t-1]); y[-1] = xp[-1] = init[d]
// ---------------------------------------------------------------------------
__global__ void chunk_end_kernel(const float* __restrict__ init_state) {
    int d = threadIdx.x;
    int c = blockIdx.x, b = blockIdx.y;
    float alpha = g_alpha[d >> 6];
    float a = 1.0f - alpha;
    int t0 = c * CHUNK;
    const __half* base = g_xp + ((size_t)b * SEQ + t0) * DIM + d;
    float prev = (t0 == 0) ? init_state[d] : __half2float(*(base - DIM));
    float l = 0.0f;
#pragma unroll 4
    for (int t = 0; t < CHUNK; t++) {
        float cur = __half2float(base[(size_t)t * DIM]);
        l = a * l + alpha * (cur - prev);
        prev = cur;
    }
    g_e[((size_t)b * NCHUNK + c) * DIM + d] = l;
}

__global__ void __launch_bounds__(512)
carry_kernel(const float* __restrict__ init_state) {
    int d = threadIdx.x;
    int b = blockIdx.x;
    float a = 1.0f - g_alpha[d >> 6];
    float aN = powf(a, (float)CHUNK);
    float e[NCHUNK];
#pragma unroll
    for (int c = 0; c < NCHUNK; c++)
        e[c] = g_e[((size_t)b * NCHUNK + c) * DIM + d];
    float carry = init_state[d];
#pragma unroll
    for (int c = 0; c < NCHUNK; c++) {
        g_cin[((size_t)b * NCHUNK + c) * DIM + d] = carry;
        carry = fmaf(aN, carry, e[c]);
    }
}

__global__ void scan_kernel(const float* __restrict__ init_state) {
    int d = threadIdx.x;
    int c = blockIdx.x, b = blockIdx.y;
    float alpha = g_alpha[d >> 6];
    float a = 1.0f - alpha;
    int t0 = c * CHUNK;
    size_t off = ((size_t)b * SEQ + t0) * DIM + d;
    const __half* base = g_xp + off;
    __half* y = g_yh + off;
    float prev = (t0 == 0) ? init_state[d] : __half2float(*(base - DIM));
    float l = g_cin[((size_t)b * NCHUNK + c) * DIM + d];
#pragma unroll 4
    for (int t = 0; t < CHUNK; t++) {
        float cur = __half2float(base[(size_t)t * DIM]);
        l = a * l + alpha * (cur - prev);
        prev = cur;
        y[(size_t)t * DIM] = __float2half_rn(l);
    }
}

// ---------------------------------------------------------------------------
// launch
// ---------------------------------------------------------------------------
extern "C" void kernel_launch(void* const* d_in, const int* in_sizes, int n_in,
                              void* d_out, int out_size) {
    const float* x    = (const float*)d_in[0];
    const float* Win  = (const float*)d_in[1];
    const float* bin  = (const float*)d_in[2];
    const float* Wout = (const float*)d_in[3];
    const float* bout = (const float*)d_in[4];
    const float* init = (const float*)d_in[5];
    const float* ap   = (const float*)d_in[6];
    float* out = (float*)d_out;

    cudaFuncSetAttribute(gemm_mma<__half>,
                         cudaFuncAttributeMaxDynamicSharedMemorySize, SMEM_TOTAL);
    cudaFuncSetAttribute(gemm_mma<float>,
                         cudaFuncAttributeMaxDynamicSharedMemorySize, SMEM_TOTAL);

    alpha_kernel<<<1, 32>>>(ap);

    __half *xh, *w1, *w2, *yh, *xp;
    cudaGetSymbolAddress((void**)&xh, g_xh);
    cudaGetSymbolAddress((void**)&w1, g_w1);
    cudaGetSymbolAddress((void**)&w2, g_w2);
    cudaGetSymbolAddress((void**)&yh, g_yh);
    cudaGetSymbolAddress((void**)&xp, g_xp);

    int n4x = (MROWS * DIM) / 4;
    convx_kernel<<<(n4x + 255) / 256, 256>>>(x, xh, n4x);
    int n4w = (DIM * DIM) / 4;
    convx_kernel<<<(n4w + 255) / 256, 256>>>(Win,  w1, n4w);
    convx_kernel<<<(n4w + 255) / 256, 256>>>(Wout, w2, n4w);

    dim3 ggrid(DIM / BN, MROWS / BM);
    gemm_mma<__half><<<ggrid, 256, SMEM_TOTAL>>>(xh, w1, bin, xp);

    chunk_end_kernel<<<dim3(NCHUNK, BATCH), DIM>>>(init);
    carry_kernel<<<BATCH, DIM>>>(init);
    scan_kernel<<<dim3(NCHUNK, BATCH), DIM>>>(init);

    gemm_mma<float><<<ggrid, 256, SMEM_TOTAL>>>(yh, w2, bout, out);
}

// round 12
// speedup vs baseline: 1.6652x; 1.0035x over previous
#include <cuda_runtime.h>
#include <cuda_fp16.h>
#include <math.h>
#include <stdint.h>

// Problem dims (fixed)
#define BATCH 4
#define SEQ   8192
#define DIM   512
#define HEADS 8
#define MROWS (BATCH*SEQ)

// scan chunking
#define CHUNK  128
#define NCHUNK (SEQ/CHUNK)

// ---------------------------------------------------------------------------
// device scratch (allocation-free rule -> __device__ globals)
// ---------------------------------------------------------------------------
__device__ __half g_xp [(size_t)MROWS*DIM];     // GEMM1 output (fp16)
__device__ __half g_xh [(size_t)MROWS*DIM];     // x as fp16
__device__ __half g_yh [(size_t)MROWS*DIM];     // y as fp16
__device__ __half g_w1 [DIM*DIM];               // W_in  fp16
__device__ __half g_w2 [DIM*DIM];               // W_out fp16
__device__ float  g_e  [(size_t)BATCH*NCHUNK*DIM];
__device__ float  g_cin[(size_t)BATCH*NCHUNK*DIM];
__device__ float  g_alpha[HEADS];

// ---------------------------------------------------------------------------
// helpers
// ---------------------------------------------------------------------------
__device__ __forceinline__ uint32_t s2u(const void* p) {
    uint32_t a;
    asm("{ .reg .u64 t; cvta.to.shared.u64 t, %1; cvt.u32.u64 %0, t; }"
        : "=r"(a) : "l"(p));
    return a;
}

__device__ __forceinline__ void ldsm4(uint32_t& r0, uint32_t& r1,
                                      uint32_t& r2, uint32_t& r3,
                                      uint32_t addr) {
    asm volatile("ldmatrix.sync.aligned.m8n8.x4.shared.b16 {%0,%1,%2,%3}, [%4];"
                 : "=r"(r0), "=r"(r1), "=r"(r2), "=r"(r3) : "r"(addr));
}

__device__ __forceinline__ void mma16816(float* c, const uint32_t* a,
                                         const uint32_t* b) {
    asm volatile(
        "mma.sync.aligned.m16n8k16.row.col.f32.f16.f16.f32 "
        "{%0,%1,%2,%3}, {%4,%5,%6,%7}, {%8,%9}, {%0,%1,%2,%3};"
        : "+f"(c[0]), "+f"(c[1]), "+f"(c[2]), "+f"(c[3])
        : "r"(a[0]), "r"(a[1]), "r"(a[2]), "r"(a[3]), "r"(b[0]), "r"(b[1]));
}

// ---------------------------------------------------------------------------
// alpha = sigmoid(alpha_param)
// ---------------------------------------------------------------------------
__global__ void alpha_kernel(const float* __restrict__ ap) {
    int h = threadIdx.x;
    if (h < HEADS) g_alpha[h] = 1.0f / (1.0f + expf(-ap[h]));
}

// ---------------------------------------------------------------------------
// fp32 -> fp16 convert (vectorized by 4)
// ---------------------------------------------------------------------------
__global__ void __launch_bounds__(256)
convx_kernel(const float* __restrict__ src, __half* __restrict__ dst, int n4) {
    int i = blockIdx.x * blockDim.x + threadIdx.x;
    if (i >= n4) return;
    float4 v = ((const float4*)src)[i];
    __half2 h0 = __halves2half2(__float2half_rn(v.x), __float2half_rn(v.y));
    __half2 h1 = __halves2half2(__float2half_rn(v.z), __float2half_rn(v.w));
    ((__half2*)(dst + 4*(size_t)i))[0] = h0;
    ((__half2*)(dst + 4*(size_t)i))[1] = h1;
}

// ---------------------------------------------------------------------------
// fp16 HMMA GEMM (R9-proven): C[m,n] = sum_k A[m,k]*B[n,k] + bias[n]
//   CTA 128x128, BK=64, 256 thr (8 warps 2x4), warp tile 64x32.
//   2-stage cp.async; xor swizzle; ldmatrix.x4; mma.m16n8k16.f16; 2 CTAs/SM.
//   Output type templated: GEMM1 -> __half (xp), GEMM2 -> float (final out).
// ---------------------------------------------------------------------------
#define BM 128
#define BN 128
#define BK 64
#define KITERS (DIM/BK)     // 8

#define XA_OFF 0
#define BB_OFF 16384
#define STAGE_BYTES 32768
#define SMEM_TOTAL (2*STAGE_BYTES)   // 64 KB

#define TSWZ(row, c16) ((uint32_t)(row) * 128u + 16u * ((uint32_t)(c16) ^ ((uint32_t)(row) & 7u)))

__device__ __forceinline__ void load_stage(uint32_t sbase,
                                           const __half* __restrict__ A,
                                           const __half* __restrict__ B,
                                           int m0, int n0, int k0, int tid) {
#pragma unroll
    for (int q = 0; q < 8; q++) {
        int i = tid + q * 256;
        int mat = i >> 10;            // 0 A, 1 B
        int j = i & 1023;
        int row = j >> 3;
        int c = j & 7;
        const __half* src = (mat ? B + (size_t)(n0 + row) * DIM
                                 : A + (size_t)(m0 + row) * DIM) + k0 + c * 8;
        uint32_t dst = sbase + (mat ? BB_OFF : XA_OFF) + TSWZ(row, c);
        asm volatile("cp.async.cg.shared.global [%0], [%1], 16;"
                     :: "r"(dst), "l"(src));
    }
}

template <typename OutT>
__global__ void __launch_bounds__(256, 2)
gemm_mma(const __half* __restrict__ A, const __half* __restrict__ B,
         const float* __restrict__ bias, OutT* __restrict__ C) {
    extern __shared__ char smem[];
    uint32_t sb = s2u(smem);

    const int tid  = threadIdx.x;
    const int wid  = tid >> 5;
    const int lane = tid & 31;
    const int wm   = wid >> 2;
    const int wn   = wid & 3;
    const int m0   = blockIdx.y * BM;
    const int n0   = blockIdx.x * BN;

    float acc[4][4][4];
#pragma unroll
    for (int i = 0; i < 4; i++)
#pragma unroll
        for (int j = 0; j < 4; j++)
#pragma unroll
            for (int r = 0; r < 4; r++) acc[i][j][r] = 0.0f;

    const int arow = wm * 64 + (lane & 15);
    const int achk = lane >> 4;
    const int brow = wn * 32 + (lane & 7) + ((lane >> 4) << 3);
    const int bchk = (lane >> 3) & 1;
    const uint32_t sxor = (uint32_t)(lane & 7);

    load_stage(sb, A, B, m0, n0, 0, tid);
    asm volatile("cp.async.commit_group;" ::: "memory");

    for (int it = 0; it < KITERS; it++) {
        if (it + 1 < KITERS) {
            load_stage(sb + ((it + 1) & 1) * STAGE_BYTES,
                       A, B, m0, n0, (it + 1) * BK, tid);
            asm volatile("cp.async.commit_group;" ::: "memory");
            asm volatile("cp.async.wait_group 1;" ::: "memory");
        } else {
            asm volatile("cp.async.wait_group 0;" ::: "memory");
        }
        __syncthreads();

        uint32_t st = sb + (it & 1) * STAGE_BYTES;
#pragma unroll
        for (int ks = 0; ks < BK / 16; ks++) {
            uint32_t av[4][4];
#pragma unroll
            for (int mt = 0; mt < 4; mt++) {
                int row = arow + mt * 16;
                uint32_t co = (uint32_t)(2 * ks + achk) ^ sxor;
                uint32_t off = (uint32_t)row * 128u + co * 16u;
                ldsm4(av[mt][0], av[mt][1], av[mt][2], av[mt][3],
                      st + XA_OFF + off);
            }
            uint32_t bv[4][2];
#pragma unroll
            for (int nt2 = 0; nt2 < 2; nt2++) {
                int row = brow + nt2 * 16;
                uint32_t co = (uint32_t)(2 * ks + bchk) ^ sxor;
                uint32_t off = (uint32_t)row * 128u + co * 16u;
                uint32_t r0, r1, r2, r3;
                ldsm4(r0, r1, r2, r3, st + BB_OFF + off);
                bv[nt2*2][0] = r0; bv[nt2*2][1] = r1;
                bv[nt2*2+1][0] = r2; bv[nt2*2+1][1] = r3;
            }
#pragma unroll
            for (int mt = 0; mt < 4; mt++)
#pragma unroll
                for (int nt = 0; nt < 4; nt++)
                    mma16816(acc[mt][nt], av[mt], bv[nt]);
        }
        __syncthreads();
    }

    const int erow = m0 + wm * 64 + (lane >> 2);
    const int ecol = n0 + wn * 32 + 2 * (lane & 3);
#pragma unroll
    for (int nt = 0; nt < 4; nt++) {
        int col = ecol + nt * 8;
        float b0 = bias[col], b1 = bias[col + 1];
#pragma unroll
        for (int mt = 0; mt < 4; mt++) {
            int row = erow + mt * 16;
            if (sizeof(OutT) == 4) {
                float2 v0 = make_float2(acc[mt][nt][0] + b0, acc[mt][nt][1] + b1);
                float2 v1 = make_float2(acc[mt][nt][2] + b0, acc[mt][nt][3] + b1);
                *(float2*)((float*)C + (size_t)row * DIM + col)       = v0;
                *(float2*)((float*)C + (size_t)(row + 8) * DIM + col) = v1;
            } else {
                __half2 h0 = __halves2half2(__float2half_rn(acc[mt][nt][0] + b0),
                                            __float2half_rn(acc[mt][nt][1] + b1));
                __half2 h1 = __halves2half2(__float2half_rn(acc[mt][nt][2] + b0),
                                            __float2half_rn(acc[mt][nt][3] + b1));
                *(__half2*)((__half*)C + (size_t)row * DIM + col)       = h0;
                *(__half2*)((__half*)C + (size_t)(row + 8) * DIM + col) = h1;
            }
        }
    }
}

// ---------------------------------------------------------------------------
// Chunked linear scan over fp16 xp:
//   y[t] = a*y[t-1] + alpha*(xp[t]-xp[t-1]); y[-1] = xp[-1] = init[d]
// ---------------------------------------------------------------------------
__global__ void chunk_end_kernel(const float* __restrict__ init_state) {
    int d = threadIdx.x;
    int c = blockIdx.x, b = blockIdx.y;
    float alpha = g_alpha[d >> 6];
    float a = 1.0f - alpha;
    int t0 = c * CHUNK;
    const __half* base = g_xp + ((size_t)b * SEQ + t0) * DIM + d;
    float prev = (t0 == 0) ? init_state[d] : __half2float(*(base - DIM));
    float l = 0.0f;
#pragma unroll 4
    for (int t = 0; t < CHUNK; t++) {
        float cur = __half2float(base[(size_t)t * DIM]);
        l = a * l + alpha * (cur - prev);
        prev = cur;
    }
    g_e[((size_t)b * NCHUNK + c) * DIM + d] = l;
}

__global__ void __launch_bounds__(512)
carry_kernel(const float* __restrict__ init_state) {
    int d = threadIdx.x;
    int b = blockIdx.x;
    float a = 1.0f - g_alpha[d >> 6];
    float aN = powf(a, (float)CHUNK);
    float e[NCHUNK];
#pragma unroll
    for (int c = 0; c < NCHUNK; c++)
        e[c] = g_e[((size_t)b * NCHUNK + c) * DIM + d];
    float carry = init_state[d];
#pragma unroll
    for (int c = 0; c < NCHUNK; c++) {
        g_cin[((size_t)b * NCHUNK + c) * DIM + d] = carry;
        carry = fmaf(aN, carry, e[c]);
    }
}

__global__ void scan_kernel(const float* __restrict__ init_state) {
    int d = threadIdx.x;
    int c = blockIdx.x, b = blockIdx.y;
    float alpha = g_alpha[d >> 6];
    float a = 1.0f - alpha;
    int t0 = c * CHUNK;
    size_t off = ((size_t)b * SEQ + t0) * DIM + d;
    const __half* base = g_xp + off;
    __half* y = g_yh + off;
    float prev = (t0 == 0) ? init_state[d] : __half2float(*(base - DIM));
    float l = g_cin[((size_t)b * NCHUNK + c) * DIM + d];
#pragma unroll 4
    for (int t = 0; t < CHUNK; t++) {
        float cur = __half2float(base[(size_t)t * DIM]);
        l = a * l + alpha * (cur - prev);
        prev = cur;
        y[(size_t)t * DIM] = __float2half_rn(l);
    }
}

// ---------------------------------------------------------------------------
// launch
// ---------------------------------------------------------------------------
extern "C" void kernel_launch(void* const* d_in, const int* in_sizes, int n_in,
                              void* d_out, int out_size) {
    const float* x    = (const float*)d_in[0];
    const float* Win  = (const float*)d_in[1];
    const float* bin  = (const float*)d_in[2];
    const float* Wout = (const float*)d_in[3];
    const float* bout = (const float*)d_in[4];
    const float* init = (const float*)d_in[5];
    const float* ap   = (const float*)d_in[6];
    float* out = (float*)d_out;

    cudaFuncSetAttribute(gemm_mma<__half>,
                         cudaFuncAttributeMaxDynamicSharedMemorySize, SMEM_TOTAL);
    cudaFuncSetAttribute(gemm_mma<float>,
                         cudaFuncAttributeMaxDynamicSharedMemorySize, SMEM_TOTAL);

    alpha_kernel<<<1, 32>>>(ap);

    __half *xh, *w1, *w2, *yh, *xp;
    cudaGetSymbolAddress((void**)&xh, g_xh);
    cudaGetSymbolAddress((void**)&w1, g_w1);
    cudaGetSymbolAddress((void**)&w2, g_w2);
    cudaGetSymbolAddress((void**)&yh, g_yh);
    cudaGetSymbolAddress((void**)&xp, g_xp);

    int n4x = (MROWS * DIM) / 4;
    convx_kernel<<<(n4x + 255) / 256, 256>>>(x, xh, n4x);
    int n4w = (DIM * DIM) / 4;
    convx_kernel<<<(n4w + 255) / 256, 256>>>(Win,  w1, n4w);
    convx_kernel<<<(n4w + 255) / 256, 256>>>(Wout, w2, n4w);

    dim3 ggrid(DIM / BN, MROWS / BM);
    gemm_mma<__half><<<ggrid, 256, SMEM_TOTAL>>>(xh, w1, bin, xp);

    chunk_end_kernel<<<dim3(NCHUNK, BATCH), DIM>>>(init);
    carry_kernel<<<BATCH, DIM>>>(init);
    scan_kernel<<<dim3(NCHUNK, BATCH), DIM>>>(init);

    gemm_mma<float><<<ggrid, 256, SMEM_TOTAL>>>(yh, w2, bout, out);
}